// round 14
// baseline (speedup 1.0000x reference)
#include <cuda_runtime.h>
#include <cuda_fp16.h>
#include <math.h>
#include <stdint.h>

// Problem constants
#define BATCH   2
#define SEQ     2048
#define HID     2048
#define NHEADS  16
#define HDIM    128
#define MTOT    (BATCH * SEQ)        // 4096

// ---------------------------------------------------------------------------
// Scratch (__device__ globals; allocation-free rule)  — single fp16 buffers
// ---------------------------------------------------------------------------
__device__ __align__(16) __half g_hs[MTOT * HID];
__device__ __align__(16) __half g_ao[MTOT * HID];
__device__ __align__(16) __half g_w[4][HID * HID];
__device__ __align__(16) __half g_q[MTOT * HID];
__device__ __align__(16) __half g_k[MTOT * HID];
__device__ __align__(16) __half g_v[MTOT * HID];

__device__ __align__(16) float g_cosT[SEQ * 64];
__device__ __align__(16) float g_sinT[SEQ * 64];

// ---------------------------------------------------------------------------
// PTX helpers (baseline PTX only — compute_103 rejects tcgen05)
// ---------------------------------------------------------------------------
static __device__ __forceinline__ uint32_t smem_u32(const void* p) {
    uint32_t a;
    asm("{ .reg .u64 t; cvta.to.shared.u64 t, %1; cvt.u32.u64 %0, t; }"
        : "=r"(a) : "l"(p));
    return a;
}

#define CPA16(d, s)  asm volatile("cp.async.cg.shared.global [%0], [%1], 16;" :: "r"(d), "l"(s) : "memory")
#define CPA_COMMIT() asm volatile("cp.async.commit_group;" ::: "memory")
#define CPA_WAIT1()  asm volatile("cp.async.wait_group 1;" ::: "memory")
#define CPA_WAIT0()  asm volatile("cp.async.wait_group 0;" ::: "memory")

static __device__ __forceinline__ void ldsm4(uint32_t* r, uint32_t addr) {
    asm volatile("ldmatrix.sync.aligned.m8n8.x4.shared.b16 {%0,%1,%2,%3}, [%4];"
                 : "=r"(r[0]), "=r"(r[1]), "=r"(r[2]), "=r"(r[3]) : "r"(addr));
}
static __device__ __forceinline__ void ldsm4t(uint32_t* r, uint32_t addr) {
    asm volatile("ldmatrix.sync.aligned.m8n8.x4.trans.shared.b16 {%0,%1,%2,%3}, [%4];"
                 : "=r"(r[0]), "=r"(r[1]), "=r"(r[2]), "=r"(r[3]) : "r"(addr));
}
// fp16 MMA, fp32 accumulate
static __device__ __forceinline__ void mma_f16(float* d, const uint32_t* a, const uint32_t* b) {
    asm volatile("mma.sync.aligned.m16n8k16.row.col.f32.f16.f16.f32 "
                 "{%0,%1,%2,%3}, {%4,%5,%6,%7}, {%8,%9}, {%0,%1,%2,%3};"
                 : "+f"(d[0]), "+f"(d[1]), "+f"(d[2]), "+f"(d[3])
                 : "r"(a[0]), "r"(a[1]), "r"(a[2]), "r"(a[3]), "r"(b[0]), "r"(b[1]));
}

static __device__ __forceinline__ uint32_t pack_h2(float a, float b) {
    __half2 t = __floats2half2_rn(a, b);
    return *reinterpret_cast<uint32_t*>(&t);
}

// ---------------------------------------------------------------------------
// Convert fp32 -> fp16
// ---------------------------------------------------------------------------
__global__ __launch_bounds__(256) void cvt_kernel(const float* __restrict__ x,
                                                  __half* __restrict__ y, int n4) {
    int i = blockIdx.x * 256 + threadIdx.x;
    if (i >= n4) return;
    float4 f = ((const float4*)x)[i];
    uint2 o;
    o.x = pack_h2(f.x, f.y);
    o.y = pack_h2(f.z, f.w);
    *reinterpret_cast<uint2*>(y + (size_t)4 * i) = o;
}

__global__ __launch_bounds__(256) void cvt_w4(
    const float* __restrict__ w0, const float* __restrict__ w1,
    const float* __restrict__ w2, const float* __restrict__ w3,
    __half* __restrict__ y, int n4) {
    int i = blockIdx.x * 256 + threadIdx.x;
    if (i >= n4) return;
    int w = blockIdx.y;
    const float* x = (w == 0) ? w0 : (w == 1) ? w1 : (w == 2) ? w2 : w3;
    size_t off = (size_t)w * (size_t)HID * HID;
    float4 f = ((const float4*)x)[i];
    uint2 o;
    o.x = pack_h2(f.x, f.y);
    o.y = pack_h2(f.z, f.w);
    *reinterpret_cast<uint2*>(y + off + (size_t)4 * i) = o;
}

// ---------------------------------------------------------------------------
// RoPE table (fp64-accurate phases)
// ---------------------------------------------------------------------------
__global__ __launch_bounds__(256) void rope_table(float* __restrict__ cosT,
                                                  float* __restrict__ sinT) {
    int idx = blockIdx.x * 256 + threadIdx.x;
    int i = idx & 63;
    int s = idx >> 6;
    double inv = pow(10000.0, -(double)i / 64.0);
    double sp, cp;
    sincos((double)s * inv, &sp, &cp);
    cosT[idx] = (float)cp;
    sinT[idx] = (float)sp;
}

// ---------------------------------------------------------------------------
// fp16 GEMM on mma.sync: C = A * B^T (K-major), CTA tile 256x128, BK=64,
// 512 threads / 16 warps, warp tile 64x32 (6 ldsm per 16 MMAs -> 25% less
// smem crossbar traffic per MMA), 3-stage cp.async, 1 CTA/SM.
// EPI 0: fp32 store (O-proj).  EPI 2: z=0/1 -> RoPE+fp16 (Q/K), z=2 -> fp16 (V).
// ---------------------------------------------------------------------------
#define BK      64
#define ASTRIDE 144                   // 128B data + 16B pad per row
#define ATILEB  (256 * ASTRIDE)       // 36864
#define BTILEB  (128 * ASTRIDE)       // 18432
#define OFF_A   0
#define OFF_B   ATILEB
#define STAGEB  (ATILEB + BTILEB)     // 55296
#define GSMEM   (3 * STAGEB)          // 165888 <= 227KB carveout (1 CTA/SM)

template <int EPI>
__global__ __launch_bounds__(512, 1) void gemm_mma(
    const __half* __restrict__ A,
    const __half* __restrict__ B0, const __half* __restrict__ B1,
    const __half* __restrict__ B2,
    float* __restrict__ C,
    __half* __restrict__ O0, __half* __restrict__ O1, __half* __restrict__ O2,
    const float* __restrict__ cosT, const float* __restrict__ sinT) {
    extern __shared__ char smem[];
    const uint32_t sb = smem_u32(smem);
    const int tid = threadIdx.x;
    const int m0 = blockIdx.y * 256, n0 = blockIdx.x * 128;
    const int lane = tid & 31, wid = tid >> 5;     // 16 warps
    const int wm = wid >> 2, wn = wid & 3;         // 4x4 grid; warp tile 64x32
    const int z = (EPI == 2) ? blockIdx.z : 0;

    const __half* B = (z == 0) ? B0 : (z == 1) ? B1 : B2;

    // Loaders. A tile: 256 rows x 8 chunks(16B) = 2048 chunks; 512 thr x 4.
    //          B tile: 128 rows x 8 chunks        = 1024 chunks; 512 thr x 2.
    const int ar = tid >> 3;            // 0..63; rows ar, ar+64, ar+128, ar+192
    const int ac = tid & 7;             // 0..7
    const uint32_t a_sofs = ar * ASTRIDE + ac * 16;
    const __half* a_gbase = A + (size_t)(m0 + ar) * HID + ac * 8;
    const uint32_t b_sofs = a_sofs;     // same pattern, rows ar, ar+64
    const __half* b_gbase = B + (size_t)(n0 + ar) * HID + ac * 8;

    float acc[4][4][4];
#pragma unroll
    for (int t = 0; t < 4; t++)
#pragma unroll
        for (int nt = 0; nt < 4; nt++)
#pragma unroll
            for (int e = 0; e < 4; e++) acc[t][nt][e] = 0.f;

    const uint32_t a_ld = sb + (uint32_t)((wm * 64 + (lane & 15)) * ASTRIDE + (lane >> 4) * 16);
    const uint32_t b_ld = sb + (uint32_t)((wn * 32 + ((lane >> 4) & 1) * 8 + (lane & 7)) * ASTRIDE
                                          + ((lane >> 3) & 1) * 16);

    const int NKT = HID / BK;   // 32

    // Prologue: stages 0, 1
#pragma unroll
    for (int p = 0; p < 2; p++) {
        uint32_t d = sb + p * STAGEB;
        size_t ge = (size_t)p * BK;
#pragma unroll
        for (int i = 0; i < 4; i++)
            CPA16(d + OFF_A + a_sofs + i * (64 * ASTRIDE), a_gbase + (size_t)i * 64 * HID + ge);
#pragma unroll
        for (int i = 0; i < 2; i++)
            CPA16(d + OFF_B + b_sofs + i * (64 * ASTRIDE), b_gbase + (size_t)i * 64 * HID + ge);
        CPA_COMMIT();
    }

    uint32_t st = 0, ld = 2 * STAGEB;
    for (int kt = 0; kt < NKT; kt++) {
        CPA_WAIT1();
        __syncthreads();   // stage st ready; all warps done computing slot ld

        if (kt + 2 < NKT) {
            uint32_t d = sb + ld;
            size_t ge = (size_t)(kt + 2) * BK;
#pragma unroll
            for (int i = 0; i < 4; i++)
                CPA16(d + OFF_A + a_sofs + i * (64 * ASTRIDE), a_gbase + (size_t)i * 64 * HID + ge);
#pragma unroll
            for (int i = 0; i < 2; i++)
                CPA16(d + OFF_B + b_sofs + i * (64 * ASTRIDE), b_gbase + (size_t)i * 64 * HID + ge);
        }
        CPA_COMMIT();

#pragma unroll
        for (int ksub = 0; ksub < 4; ksub++) {
            const uint32_t ko = ksub * 32;
            uint32_t ah[4][4];
#pragma unroll
            for (int t = 0; t < 4; t++)
                ldsm4(ah[t], a_ld + st + OFF_A + t * (16 * ASTRIDE) + ko);
#pragma unroll
            for (int p = 0; p < 2; p++) {
                uint32_t bh[4];
                ldsm4(bh, b_ld + st + OFF_B + p * (16 * ASTRIDE) + ko);
#pragma unroll
                for (int t = 0; t < 4; t++)
#pragma unroll
                    for (int hf = 0; hf < 2; hf++)
                        mma_f16(acc[t][p * 2 + hf], ah[t], &bh[hf * 2]);
            }
        }
        st += STAGEB; if (st == 3 * STAGEB) st = 0;
        ld += STAGEB; if (ld == 3 * STAGEB) ld = 0;
    }

    if (EPI == 0) {
#pragma unroll
        for (int t = 0; t < 4; t++) {
            int row = m0 + wm * 64 + t * 16 + (lane >> 2);
#pragma unroll
            for (int nt = 0; nt < 4; nt++) {
                int col = n0 + wn * 32 + nt * 8 + (lane & 3) * 2;
                *(float2*)&C[(size_t)row * HID + col] =
                    make_float2(acc[t][nt][0], acc[t][nt][1]);
                *(float2*)&C[(size_t)(row + 8) * HID + col] =
                    make_float2(acc[t][nt][2], acc[t][nt][3]);
            }
        }
    } else if (z == 2) {
        // V projection: fp16 store from registers
#pragma unroll
        for (int t = 0; t < 4; t++) {
            int row = m0 + wm * 64 + t * 16 + (lane >> 2);
#pragma unroll
            for (int nt = 0; nt < 4; nt++) {
                int col = n0 + wn * 32 + nt * 8 + (lane & 3) * 2;
                *(uint32_t*)&O2[(size_t)row * HID + col]       = pack_h2(acc[t][nt][0], acc[t][nt][1]);
                *(uint32_t*)&O2[(size_t)(row + 8) * HID + col] = pack_h2(acc[t][nt][2], acc[t][nt][3]);
            }
        }
    } else {
        // Q/K projection: RoPE + fp16 via smem staging (256x132 fp32 = 135168 <= GSMEM)
        __half* O = z ? O1 : O0;
        float* smf = (float*)smem;
        CPA_WAIT0();
        __syncthreads();               // pending async copies drained; smem reusable
#pragma unroll
        for (int t = 0; t < 4; t++) {
            int r = wm * 64 + t * 16 + (lane >> 2);
            int c = wn * 32 + (lane & 3) * 2;
#pragma unroll
            for (int nt = 0; nt < 4; nt++) {
                int cc = c + nt * 8;
                smf[r * 132 + cc]       = acc[t][nt][0];
                smf[r * 132 + cc + 1]   = acc[t][nt][1];
                smf[(r + 8) * 132 + cc]     = acc[t][nt][2];
                smf[(r + 8) * 132 + cc + 1] = acc[t][nt][3];
            }
        }
        __syncthreads();
#pragma unroll
        for (int it = 0; it < 16; it++) {
            int p = it * 512 + tid;        // [0, 8192)
            int row = p >> 5;              // 0..255
            int i2 = (p & 31) * 2;
            float2 x1 = *(float2*)&smf[row * 132 + i2];
            float2 x2 = *(float2*)&smf[row * 132 + 64 + i2];
            int grow = m0 + row;
            int s = grow & (SEQ - 1);
            float2 cs = *(const float2*)&cosT[s * 64 + i2];
            float2 sn = *(const float2*)&sinT[s * 64 + i2];
            float r1a = x1.x * cs.x - x2.x * sn.x;
            float r1b = x1.y * cs.y - x2.y * sn.y;
            float r2a = x2.x * cs.x + x1.x * sn.x;
            float r2b = x2.y * cs.y + x1.y * sn.y;
            size_t o1 = (size_t)grow * HID + n0 + i2;
            *(uint32_t*)&O[o1]      = pack_h2(r1a, r1b);
            *(uint32_t*)&O[o1 + 64] = pack_h2(r2a, r2b);
        }
    }
}

// ---------------------------------------------------------------------------
// fp16 tensor-core flash attention (causal) — R13 version (KV double-buffered,
// Q slot reused as buffer 1, 3 CTAs/SM, one barrier per j-iteration).
// ---------------------------------------------------------------------------
#define AST    272                   // bytes per smem row (128 fp16 + 16 pad)
#define ATILE  (64 * AST)            // 17408
#define ASMEM  (4 * ATILE)           // 69632; 3 CTAs = 208896 <= 228KB

__global__ __launch_bounds__(128, 3) void attn_tc(
    const __half* __restrict__ q, const __half* __restrict__ k,
    const __half* __restrict__ v, __half* __restrict__ ao) {
    extern __shared__ char smc[];
    const uint32_t sb = smem_u32(smc);
    const int tid = threadIdx.x, lane = tid & 31, wid = tid >> 5;
    const int qt = gridDim.x - 1 - blockIdx.x;     // heavy tiles first
    const int bh = blockIdx.y;
    const int b = bh >> 4, h = bh & 15;
    const size_t hoff = (size_t)b * SEQ * HID + (size_t)h * HDIM;

    // Prologue: Q tile -> slot 2 (own group), then KV(0) -> slots 0,1 (group)
    {
        const size_t qbase = hoff + (size_t)(qt * 64) * HID;
#pragma unroll
        for (int i = 0; i < 8; i++) {
            int idx = i * 128 + tid, row = idx >> 4, c16 = idx & 15;
            uint32_t so = row * AST + c16 * 16;
            CPA16(sb + 2 * ATILE + so, q + qbase + (size_t)row * HID + c16 * 8);
        }
        CPA_COMMIT();
#pragma unroll
        for (int i = 0; i < 8; i++) {
            int idx = i * 128 + tid, row = idx >> 4, c16 = idx & 15;
            uint32_t so = row * AST + c16 * 16;
            size_t go = hoff + (size_t)row * HID + c16 * 8;
            CPA16(sb + 0 * ATILE + so, k + go);
            CPA16(sb + 1 * ATILE + so, v + go);
        }
        CPA_COMMIT();
    }

    const uint32_t a_q = sb + (uint32_t)((wid * 16 + (lane & 15)) * AST + (lane >> 4) * 16);
    const uint32_t b_kr = sb + (uint32_t)((((lane & 7) + ((lane >> 4) & 1) * 8)) * AST + ((lane >> 3) & 1) * 16);
    const uint32_t b_vr = sb + (uint32_t)((((lane & 7) + ((lane >> 3) & 1) * 8)) * AST + ((lane >> 4) & 1) * 16);

    CPA_WAIT1();
    __syncthreads();
    uint32_t aQf[8][4];
#pragma unroll
    for (int ks = 0; ks < 8; ks++)
        ldsm4(aQf[ks], a_q + 2 * ATILE + ks * 32);
    __syncthreads();   // all warps done reading slot 2 (Q) — safe to reuse as K1

    float o[16][4];
#pragma unroll
    for (int nt = 0; nt < 16; nt++)
#pragma unroll
        for (int e = 0; e < 4; e++) o[nt][e] = 0.f;
    float m0 = -1e30f, m1 = -1e30f, l0 = 0.f, l1 = 0.f;
    const float scale = 0.08838834764831845f;

    const int grow0 = qt * 64 + wid * 16 + (lane >> 2);

    for (int j = 0; j <= qt; j++) {
        CPA_WAIT0();
        __syncthreads();    // KV(j) visible; all warps done with buf (j-1)&1

        if (j < qt) {       // prefetch KV(j+1) into buf (j+1)&1
            const size_t kbase = hoff + (size_t)((j + 1) * 64) * HID;
            const uint32_t kslot = ((j + 1) & 1) * 2 * ATILE;
#pragma unroll
            for (int i = 0; i < 8; i++) {
                int idx = i * 128 + tid, row = idx >> 4, c16 = idx & 15;
                uint32_t so = row * AST + c16 * 16;
                size_t go = kbase + (size_t)row * HID + c16 * 8;
                CPA16(sb + kslot + so,         k + go);
                CPA16(sb + kslot + ATILE + so, v + go);
            }
            CPA_COMMIT();
        }

        const uint32_t kO = (j & 1) * 2 * ATILE;
        const uint32_t vO = kO + ATILE;

        // S = Q K^T
        float s[8][4];
#pragma unroll
        for (int nt = 0; nt < 8; nt++)
#pragma unroll
            for (int e = 0; e < 4; e++) s[nt][e] = 0.f;

#pragma unroll
        for (int ks = 0; ks < 8; ks++) {
#pragma unroll
            for (int g = 0; g < 4; g++) {
                uint32_t bK[4];
                ldsm4(bK, b_kr + kO + g * (16 * AST) + ks * 32);
                mma_f16(s[2 * g],     aQf[ks], bK);
                mma_f16(s[2 * g + 1], aQf[ks], bK + 2);
            }
        }

        // Online softmax
        const bool diag = (j == qt);
        float mx0 = -1e30f, mx1 = -1e30f;
#pragma unroll
        for (int nt = 0; nt < 8; nt++) {
            int c0 = j * 64 + nt * 8 + (lane & 3) * 2;
#pragma unroll
            for (int e = 0; e < 4; e++) {
                float val = s[nt][e] * scale;
                if (diag && (c0 + (e & 1)) > (grow0 + (e >> 1) * 8)) val = -1e30f;
                s[nt][e] = val;
            }
            mx0 = fmaxf(mx0, fmaxf(s[nt][0], s[nt][1]));
            mx1 = fmaxf(mx1, fmaxf(s[nt][2], s[nt][3]));
        }
        mx0 = fmaxf(mx0, __shfl_xor_sync(0xffffffffu, mx0, 1));
        mx0 = fmaxf(mx0, __shfl_xor_sync(0xffffffffu, mx0, 2));
        mx1 = fmaxf(mx1, __shfl_xor_sync(0xffffffffu, mx1, 1));
        mx1 = fmaxf(mx1, __shfl_xor_sync(0xffffffffu, mx1, 2));
        float mn0 = fmaxf(m0, mx0), mn1 = fmaxf(m1, mx1);
        float cr0 = __expf(m0 - mn0), cr1 = __expf(m1 - mn1);
        m0 = mn0; m1 = mn1;
        float sum0 = 0.f, sum1 = 0.f;
#pragma unroll
        for (int nt = 0; nt < 8; nt++) {
            s[nt][0] = __expf(s[nt][0] - mn0);
            s[nt][1] = __expf(s[nt][1] - mn0);
            s[nt][2] = __expf(s[nt][2] - mn1);
            s[nt][3] = __expf(s[nt][3] - mn1);
            sum0 += s[nt][0] + s[nt][1];
            sum1 += s[nt][2] + s[nt][3];
        }
        sum0 += __shfl_xor_sync(0xffffffffu, sum0, 1);
        sum0 += __shfl_xor_sync(0xffffffffu, sum0, 2);
        sum1 += __shfl_xor_sync(0xffffffffu, sum1, 1);
        sum1 += __shfl_xor_sync(0xffffffffu, sum1, 2);
        l0 = l0 * cr0 + sum0;
        l1 = l1 * cr1 + sum1;
#pragma unroll
        for (int nt = 0; nt < 16; nt++) {
            o[nt][0] *= cr0; o[nt][1] *= cr0;
            o[nt][2] *= cr1; o[nt][3] *= cr1;
        }

        // O += P V
#pragma unroll
        for (int kc = 0; kc < 4; kc++) {
            uint32_t pH[4];
            pH[0] = pack_h2(s[2 * kc][0],     s[2 * kc][1]);
            pH[1] = pack_h2(s[2 * kc][2],     s[2 * kc][3]);
            pH[2] = pack_h2(s[2 * kc + 1][0], s[2 * kc + 1][1]);
            pH[3] = pack_h2(s[2 * kc + 1][2], s[2 * kc + 1][3]);

            uint32_t vbase = b_vr + vO + kc * (16 * AST);
#pragma unroll
            for (int ng = 0; ng < 8; ng++) {
                uint32_t vH[4];
                ldsm4t(vH, vbase + ng * 32);
                mma_f16(o[2 * ng],     pH, vH);
                mma_f16(o[2 * ng + 1], pH, vH + 2);
            }
        }
    }

    // Epilogue: normalize, fp16 store
    float inv0 = 1.f / l0, inv1 = 1.f / l1;
    int row0 = b * SEQ + qt * 64 + wid * 16 + (lane >> 2);
#pragma unroll
    for (int nt = 0; nt < 16; nt++) {
        int col = h * HDIM + nt * 8 + (lane & 3) * 2;
        *(uint32_t*)&ao[(size_t)row0 * HID + col] =
            pack_h2(o[nt][0] * inv0, o[nt][1] * inv0);
        *(uint32_t*)&ao[(size_t)(row0 + 8) * HID + col] =
            pack_h2(o[nt][2] * inv1, o[nt][3] * inv1);
    }
}

// ---------------------------------------------------------------------------
// Launch
// ---------------------------------------------------------------------------
extern "C" void kernel_launch(void* const* d_in, const int* in_sizes, int n_in,
                              void* d_out, int out_size) {
    const float* hs = (const float*)d_in[0];
    const float* Wq = (const float*)d_in[1];
    const float* Wk = (const float*)d_in[2];
    const float* Wv = (const float*)d_in[3];
    const float* Wo = (const float*)d_in[4];
    float* out = (float*)d_out;

    float *cosT, *sinT;
    cudaGetSymbolAddress((void**)&cosT, g_cosT);
    cudaGetSymbolAddress((void**)&sinT, g_sinT);

    __half *hsp, *aop, *wp, *qp, *kp, *vp;
    cudaGetSymbolAddress((void**)&hsp, g_hs);
    cudaGetSymbolAddress((void**)&aop, g_ao);
    cudaGetSymbolAddress((void**)&wp,  g_w);
    cudaGetSymbolAddress((void**)&qp,  g_q);
    cudaGetSymbolAddress((void**)&kp,  g_k);
    cudaGetSymbolAddress((void**)&vp,  g_v);

    const size_t WN = (size_t)HID * HID;
    const int n4_hs = MTOT * HID / 4;
    const int n4_w  = (int)(WN / 4);

    cvt_kernel<<<(n4_hs + 255) / 256, 256>>>(hs, hsp, n4_hs);
    cvt_w4<<<dim3((n4_w + 255) / 256, 4), 256>>>(Wq, Wk, Wv, Wo, wp, n4_w);
    rope_table<<<(SEQ * 64) / 256, 256>>>(cosT, sinT);

    cudaFuncSetAttribute(gemm_mma<0>, cudaFuncAttributeMaxDynamicSharedMemorySize, GSMEM);
    cudaFuncSetAttribute(gemm_mma<2>, cudaFuncAttributeMaxDynamicSharedMemorySize, GSMEM);

    dim3 gg(HID / 128, MTOT / 256);          // (16, 16)
    dim3 gg3(HID / 128, MTOT / 256, 3);      // Q, K, V in one launch

    // QKV projections: z=0 -> Q (RoPE), z=1 -> K (RoPE), z=2 -> V
    gemm_mma<2><<<gg3, 512, GSMEM>>>(hsp,
                                     wp + 0 * WN, wp + 1 * WN, wp + 2 * WN,
                                     nullptr,
                                     qp, kp, vp, cosT, sinT);

    cudaFuncSetAttribute(attn_tc, cudaFuncAttributeMaxDynamicSharedMemorySize, ASMEM);
    attn_tc<<<dim3(SEQ / 64, BATCH * NHEADS), 128, ASMEM>>>(qp, kp, vp, aop);

    // Output projection, fp32 store
    gemm_mma<0><<<gg, 512, GSMEM>>>(aop,
                                    wp + 3 * WN, nullptr, nullptr,
                                    out,
                                    nullptr, nullptr, nullptr,
                                    nullptr, nullptr);
}

// round 15
// speedup vs baseline: 1.1456x; 1.1456x over previous
#include <cuda_runtime.h>
#include <cuda_fp16.h>
#include <math.h>
#include <stdint.h>

// Problem constants
#define BATCH   2
#define SEQ     2048
#define HID     2048
#define NHEADS  16
#define HDIM    128
#define MTOT    (BATCH * SEQ)        // 4096

// ---------------------------------------------------------------------------
// Scratch (__device__ globals; allocation-free rule)  — single fp16 buffers
// ---------------------------------------------------------------------------
__device__ __align__(16) __half g_hs[MTOT * HID];
__device__ __align__(16) __half g_ao[MTOT * HID];
__device__ __align__(16) __half g_w[4][HID * HID];
__device__ __align__(16) __half g_q[MTOT * HID];
__device__ __align__(16) __half g_k[MTOT * HID];
__device__ __align__(16) __half g_v[MTOT * HID];

__device__ __align__(16) float g_cosT[SEQ * 64];
__device__ __align__(16) float g_sinT[SEQ * 64];

// ---------------------------------------------------------------------------
// PTX helpers (baseline PTX only — compute_103 rejects tcgen05)
// ---------------------------------------------------------------------------
static __device__ __forceinline__ uint32_t smem_u32(const void* p) {
    uint32_t a;
    asm("{ .reg .u64 t; cvta.to.shared.u64 t, %1; cvt.u32.u64 %0, t; }"
        : "=r"(a) : "l"(p));
    return a;
}

#define CPA16(d, s)  asm volatile("cp.async.cg.shared.global [%0], [%1], 16;" :: "r"(d), "l"(s) : "memory")
#define CPA_COMMIT() asm volatile("cp.async.commit_group;" ::: "memory")
#define CPA_WAIT1()  asm volatile("cp.async.wait_group 1;" ::: "memory")
#define CPA_WAIT0()  asm volatile("cp.async.wait_group 0;" ::: "memory")

static __device__ __forceinline__ void ldsm4(uint32_t* r, uint32_t addr) {
    asm volatile("ldmatrix.sync.aligned.m8n8.x4.shared.b16 {%0,%1,%2,%3}, [%4];"
                 : "=r"(r[0]), "=r"(r[1]), "=r"(r[2]), "=r"(r[3]) : "r"(addr));
}
static __device__ __forceinline__ void ldsm4t(uint32_t* r, uint32_t addr) {
    asm volatile("ldmatrix.sync.aligned.m8n8.x4.trans.shared.b16 {%0,%1,%2,%3}, [%4];"
                 : "=r"(r[0]), "=r"(r[1]), "=r"(r[2]), "=r"(r[3]) : "r"(addr));
}
// fp16 MMA, fp32 accumulate
static __device__ __forceinline__ void mma_f16(float* d, const uint32_t* a, const uint32_t* b) {
    asm volatile("mma.sync.aligned.m16n8k16.row.col.f32.f16.f16.f32 "
                 "{%0,%1,%2,%3}, {%4,%5,%6,%7}, {%8,%9}, {%0,%1,%2,%3};"
                 : "+f"(d[0]), "+f"(d[1]), "+f"(d[2]), "+f"(d[3])
                 : "r"(a[0]), "r"(a[1]), "r"(a[2]), "r"(a[3]), "r"(b[0]), "r"(b[1]));
}

static __device__ __forceinline__ uint32_t pack_h2(float a, float b) {
    __half2 t = __floats2half2_rn(a, b);
    return *reinterpret_cast<uint32_t*>(&t);
}
// pack two fp32 -> f16x2 (lo = a, hi = b) via single cvt
static __device__ __forceinline__ uint32_t cvt_h2(float a, float b) {
    uint32_t r;
    asm("cvt.rn.f16x2.f32 %0, %1, %2;" : "=r"(r) : "f"(b), "f"(a));
    return r;
}
static __device__ __forceinline__ uint32_t ex2_h2(uint32_t x) {
    uint32_t r;
    asm("ex2.approx.f16x2 %0, %1;" : "=r"(r) : "r"(x));
    return r;
}

// ---------------------------------------------------------------------------
// Convert fp32 -> fp16
// ---------------------------------------------------------------------------
__global__ __launch_bounds__(256) void cvt_kernel(const float* __restrict__ x,
                                                  __half* __restrict__ y, int n4) {
    int i = blockIdx.x * 256 + threadIdx.x;
    if (i >= n4) return;
    float4 f = ((const float4*)x)[i];
    uint2 o;
    o.x = pack_h2(f.x, f.y);
    o.y = pack_h2(f.z, f.w);
    *reinterpret_cast<uint2*>(y + (size_t)4 * i) = o;
}

__global__ __launch_bounds__(256) void cvt_w4(
    const float* __restrict__ w0, const float* __restrict__ w1,
    const float* __restrict__ w2, const float* __restrict__ w3,
    __half* __restrict__ y, int n4) {
    int i = blockIdx.x * 256 + threadIdx.x;
    if (i >= n4) return;
    int w = blockIdx.y;
    const float* x = (w == 0) ? w0 : (w == 1) ? w1 : (w == 2) ? w2 : w3;
    size_t off = (size_t)w * (size_t)HID * HID;
    float4 f = ((const float4*)x)[i];
    uint2 o;
    o.x = pack_h2(f.x, f.y);
    o.y = pack_h2(f.z, f.w);
    *reinterpret_cast<uint2*>(y + off + (size_t)4 * i) = o;
}

// ---------------------------------------------------------------------------
// RoPE table (fp64-accurate phases)
// ---------------------------------------------------------------------------
__global__ __launch_bounds__(256) void rope_table(float* __restrict__ cosT,
                                                  float* __restrict__ sinT) {
    int idx = blockIdx.x * 256 + threadIdx.x;
    int i = idx & 63;
    int s = idx >> 6;
    double inv = pow(10000.0, -(double)i / 64.0);
    double sp, cp;
    sincos((double)s * inv, &sp, &cp);
    cosT[idx] = (float)cp;
    sinT[idx] = (float)sp;
}

// ---------------------------------------------------------------------------
// fp16 GEMM on mma.sync (exact R13 config, 295 us): C = A * B^T (K-major),
// CTA tile 128x128, BK=64, 512 threads / 16 warps, warp tile 32x32,
// 3-stage cp.async pipeline, one barrier per K-iter, 2 CTAs/SM.
// EPI 0: fp32 store (O-proj).  EPI 2: z=0/1 -> RoPE+fp16 (Q/K), z=2 -> fp16 (V).
// ---------------------------------------------------------------------------
#define BK      64
#define ASTRIDE 144                   // 128B data + 16B pad per row
#define TILEB   (128 * ASTRIDE)       // 18432
#define OFF_A   0
#define OFF_B   TILEB
#define STAGEB  (2 * TILEB)           // 36864
#define GSMEM   (3 * STAGEB)          // 110592; 2 CTAs = 221184 <= 228KB carveout

template <int EPI>
__global__ __launch_bounds__(512, 2) void gemm_mma(
    const __half* __restrict__ A,
    const __half* __restrict__ B0, const __half* __restrict__ B1,
    const __half* __restrict__ B2,
    float* __restrict__ C,
    __half* __restrict__ O0, __half* __restrict__ O1, __half* __restrict__ O2,
    const float* __restrict__ cosT, const float* __restrict__ sinT) {
    extern __shared__ char smem[];
    const uint32_t sb = smem_u32(smem);
    const int tid = threadIdx.x;
    const int m0 = blockIdx.y * 128, n0 = blockIdx.x * 128;
    const int lane = tid & 31, wid = tid >> 5;     // 16 warps
    const int wm = wid >> 2, wn = wid & 3;         // 4x4 warp grid, 32x32 tiles
    const int z = (EPI == 2) ? blockIdx.z : 0;

    const __half* B = (z == 0) ? B0 : (z == 1) ? B1 : B2;

    // Loader: tile = 128 rows x 128B = 1024 chunks of 16B; 512 threads x 2 chunks.
    const int lrow = tid >> 3;          // 0..63  (second chunk at row+64)
    const int lc16 = tid & 7;           // 0..7
    const uint32_t sofs  = lrow * ASTRIDE + lc16 * 16;
    const uint32_t sofs2 = (lrow + 64) * ASTRIDE + lc16 * 16;

    const __half* a_base  = A + (size_t)(m0 + lrow) * HID + lc16 * 8;
    const __half* a_base2 = A + (size_t)(m0 + lrow + 64) * HID + lc16 * 8;
    const __half* b_base  = B + (size_t)(n0 + lrow) * HID + lc16 * 8;
    const __half* b_base2 = B + (size_t)(n0 + lrow + 64) * HID + lc16 * 8;

    float acc[2][4][4];
#pragma unroll
    for (int t = 0; t < 2; t++)
#pragma unroll
        for (int nt = 0; nt < 4; nt++)
#pragma unroll
            for (int e = 0; e < 4; e++) acc[t][nt][e] = 0.f;

    const uint32_t a_ld = sb + (uint32_t)((wm * 32 + (lane & 15)) * ASTRIDE + (lane >> 4) * 16);
    const uint32_t b_ld = sb + (uint32_t)((wn * 32 + ((lane >> 4) & 1) * 8 + (lane & 7)) * ASTRIDE
                                          + ((lane >> 3) & 1) * 16);

    const int NKT = HID / BK;   // 32

    // Prologue: stages 0, 1
#pragma unroll
    for (int p = 0; p < 2; p++) {
        uint32_t d = sb + p * STAGEB;
        size_t ge = (size_t)p * BK;
        CPA16(d + OFF_A + sofs,  a_base  + ge);
        CPA16(d + OFF_A + sofs2, a_base2 + ge);
        CPA16(d + OFF_B + sofs,  b_base  + ge);
        CPA16(d + OFF_B + sofs2, b_base2 + ge);
        CPA_COMMIT();
    }

    uint32_t st = 0, ld = 2 * STAGEB;
    for (int kt = 0; kt < NKT; kt++) {
        CPA_WAIT1();
        __syncthreads();   // stage st ready; all warps done computing slot ld

        if (kt + 2 < NKT) {
            uint32_t d = sb + ld;
            size_t ge = (size_t)(kt + 2) * BK;
            CPA16(d + OFF_A + sofs,  a_base  + ge);
            CPA16(d + OFF_A + sofs2, a_base2 + ge);
            CPA16(d + OFF_B + sofs,  b_base  + ge);
            CPA16(d + OFF_B + sofs2, b_base2 + ge);
        }
        CPA_COMMIT();

#pragma unroll
        for (int ksub = 0; ksub < 4; ksub++) {
            const uint32_t ko = ksub * 32;
            uint32_t ah[2][4];
#pragma unroll
            for (int t = 0; t < 2; t++)
                ldsm4(ah[t], a_ld + st + OFF_A + t * (16 * ASTRIDE) + ko);
#pragma unroll
            for (int p = 0; p < 2; p++) {
                uint32_t bh[4];
                ldsm4(bh, b_ld + st + OFF_B + p * (16 * ASTRIDE) + ko);
#pragma unroll
                for (int t = 0; t < 2; t++)
#pragma unroll
                    for (int hf = 0; hf < 2; hf++)
                        mma_f16(acc[t][p * 2 + hf], ah[t], &bh[hf * 2]);
            }
        }
        st += STAGEB; if (st == 3 * STAGEB) st = 0;
        ld += STAGEB; if (ld == 3 * STAGEB) ld = 0;
    }

    if (EPI == 0) {
#pragma unroll
        for (int t = 0; t < 2; t++) {
            int row = m0 + wm * 32 + t * 16 + (lane >> 2);
#pragma unroll
            for (int nt = 0; nt < 4; nt++) {
                int col = n0 + wn * 32 + nt * 8 + (lane & 3) * 2;
                *(float2*)&C[(size_t)row * HID + col] =
                    make_float2(acc[t][nt][0], acc[t][nt][1]);
                *(float2*)&C[(size_t)(row + 8) * HID + col] =
                    make_float2(acc[t][nt][2], acc[t][nt][3]);
            }
        }
    } else if (z == 2) {
        // V projection: fp16 store from registers
#pragma unroll
        for (int t = 0; t < 2; t++) {
            int row = m0 + wm * 32 + t * 16 + (lane >> 2);
#pragma unroll
            for (int nt = 0; nt < 4; nt++) {
                int col = n0 + wn * 32 + nt * 8 + (lane & 3) * 2;
                *(uint32_t*)&O2[(size_t)row * HID + col]       = pack_h2(acc[t][nt][0], acc[t][nt][1]);
                *(uint32_t*)&O2[(size_t)(row + 8) * HID + col] = pack_h2(acc[t][nt][2], acc[t][nt][3]);
            }
        }
    } else {
        // Q/K projection: RoPE + fp16 via smem staging
        __half* O = z ? O1 : O0;
        float* smf = (float*)smem;     // [128][132] fp32 = 67584 B <= GSMEM
        CPA_WAIT0();
        __syncthreads();               // all pending async copies drained; smem reusable
#pragma unroll
        for (int t = 0; t < 2; t++) {
            int r = wm * 32 + t * 16 + (lane >> 2);
            int c = wn * 32 + (lane & 3) * 2;
#pragma unroll
            for (int nt = 0; nt < 4; nt++) {
                int cc = c + nt * 8;
                smf[r * 132 + cc]       = acc[t][nt][0];
                smf[r * 132 + cc + 1]   = acc[t][nt][1];
                smf[(r + 8) * 132 + cc]     = acc[t][nt][2];
                smf[(r + 8) * 132 + cc + 1] = acc[t][nt][3];
            }
        }
        __syncthreads();
#pragma unroll
        for (int it = 0; it < 8; it++) {
            int p = it * 512 + tid;        // [0, 4096)
            int row = p >> 5;
            int i2 = (p & 31) * 2;
            float2 x1 = *(float2*)&smf[row * 132 + i2];
            float2 x2 = *(float2*)&smf[row * 132 + 64 + i2];
            int grow = m0 + row;
            int s = grow & (SEQ - 1);
            float2 cs = *(const float2*)&cosT[s * 64 + i2];
            float2 sn = *(const float2*)&sinT[s * 64 + i2];
            float r1a = x1.x * cs.x - x2.x * sn.x;
            float r1b = x1.y * cs.y - x2.y * sn.y;
            float r2a = x2.x * cs.x + x1.x * sn.x;
            float r2b = x2.y * cs.y + x1.y * sn.y;
            size_t o1 = (size_t)grow * HID + n0 + i2;
            *(uint32_t*)&O[o1]      = pack_h2(r1a, r1b);
            *(uint32_t*)&O[o1 + 64] = pack_h2(r2a, r2b);
        }
    }
}

// ---------------------------------------------------------------------------
// fp16 tensor-core flash attention (causal), R13 structure (KV double-buffered,
// Q slot reused as buffer 1, 3 CTAs/SM, one barrier per j-iteration) +
// softmax exp via ex2.approx.f16x2 (halves MUFU; P frags come out directly).
// ---------------------------------------------------------------------------
#define AST    272                   // bytes per smem row (128 fp16 + 16 pad)
#define ATILE  (64 * AST)            // 17408
#define ASMEM  (4 * ATILE)           // 69632; 3 CTAs = 208896 <= 228KB

__global__ __launch_bounds__(128, 3) void attn_tc(
    const __half* __restrict__ q, const __half* __restrict__ k,
    const __half* __restrict__ v, __half* __restrict__ ao) {
    extern __shared__ char smc[];
    const uint32_t sb = smem_u32(smc);
    const int tid = threadIdx.x, lane = tid & 31, wid = tid >> 5;
    const int qt = gridDim.x - 1 - blockIdx.x;     // heavy tiles first
    const int bh = blockIdx.y;
    const int b = bh >> 4, h = bh & 15;
    const size_t hoff = (size_t)b * SEQ * HID + (size_t)h * HDIM;

    // Prologue: Q tile -> slot 2 (own group), then KV(0) -> slots 0,1 (group)
    {
        const size_t qbase = hoff + (size_t)(qt * 64) * HID;
#pragma unroll
        for (int i = 0; i < 8; i++) {
            int idx = i * 128 + tid, row = idx >> 4, c16 = idx & 15;
            uint32_t so = row * AST + c16 * 16;
            CPA16(sb + 2 * ATILE + so, q + qbase + (size_t)row * HID + c16 * 8);
        }
        CPA_COMMIT();
#pragma unroll
        for (int i = 0; i < 8; i++) {
            int idx = i * 128 + tid, row = idx >> 4, c16 = idx & 15;
            uint32_t so = row * AST + c16 * 16;
            size_t go = hoff + (size_t)row * HID + c16 * 8;
            CPA16(sb + 0 * ATILE + so, k + go);
            CPA16(sb + 1 * ATILE + so, v + go);
        }
        CPA_COMMIT();
    }

    const uint32_t a_q = sb + (uint32_t)((wid * 16 + (lane & 15)) * AST + (lane >> 4) * 16);
    const uint32_t b_kr = sb + (uint32_t)((((lane & 7) + ((lane >> 4) & 1) * 8)) * AST + ((lane >> 3) & 1) * 16);
    const uint32_t b_vr = sb + (uint32_t)((((lane & 7) + ((lane >> 3) & 1) * 8)) * AST + ((lane >> 4) & 1) * 16);

    CPA_WAIT1();
    __syncthreads();
    uint32_t aQf[8][4];
#pragma unroll
    for (int ks = 0; ks < 8; ks++)
        ldsm4(aQf[ks], a_q + 2 * ATILE + ks * 32);
    __syncthreads();   // all warps done reading slot 2 (Q) — safe to reuse as K1

    float o[16][4];
#pragma unroll
    for (int nt = 0; nt < 16; nt++)
#pragma unroll
        for (int e = 0; e < 4; e++) o[nt][e] = 0.f;
    float m0 = -1e30f, m1 = -1e30f, l0 = 0.f, l1 = 0.f;
    const float scale = 0.08838834764831845f;
    const float L2E = 1.4426950408889634f;

    const int grow0 = qt * 64 + wid * 16 + (lane >> 2);

    for (int j = 0; j <= qt; j++) {
        CPA_WAIT0();
        __syncthreads();    // KV(j) visible; all warps done with buf (j-1)&1

        if (j < qt) {       // prefetch KV(j+1) into buf (j+1)&1
            const size_t kbase = hoff + (size_t)((j + 1) * 64) * HID;
            const uint32_t kslot = ((j + 1) & 1) * 2 * ATILE;
#pragma unroll
            for (int i = 0; i < 8; i++) {
                int idx = i * 128 + tid, row = idx >> 4, c16 = idx & 15;
                uint32_t so = row * AST + c16 * 16;
                size_t go = kbase + (size_t)row * HID + c16 * 8;
                CPA16(sb + kslot + so,         k + go);
                CPA16(sb + kslot + ATILE + so, v + go);
            }
            CPA_COMMIT();
        }

        const uint32_t kO = (j & 1) * 2 * ATILE;
        const uint32_t vO = kO + ATILE;

        // S = Q K^T
        float s[8][4];
#pragma unroll
        for (int nt = 0; nt < 8; nt++)
#pragma unroll
            for (int e = 0; e < 4; e++) s[nt][e] = 0.f;

#pragma unroll
        for (int ks = 0; ks < 8; ks++) {
#pragma unroll
            for (int g = 0; g < 4; g++) {
                uint32_t bK[4];
                ldsm4(bK, b_kr + kO + g * (16 * AST) + ks * 32);
                mma_f16(s[2 * g],     aQf[ks], bK);
                mma_f16(s[2 * g + 1], aQf[ks], bK + 2);
            }
        }

        // Online softmax (exp in fp16 via ex2.approx.f16x2)
        const bool diag = (j == qt);
        float mx0 = -1e30f, mx1 = -1e30f;
#pragma unroll
        for (int nt = 0; nt < 8; nt++) {
            int c0 = j * 64 + nt * 8 + (lane & 3) * 2;
#pragma unroll
            for (int e = 0; e < 4; e++) {
                float val = s[nt][e] * scale;
                if (diag && (c0 + (e & 1)) > (grow0 + (e >> 1) * 8)) val = -1e30f;
                s[nt][e] = val;
            }
            mx0 = fmaxf(mx0, fmaxf(s[nt][0], s[nt][1]));
            mx1 = fmaxf(mx1, fmaxf(s[nt][2], s[nt][3]));
        }
        mx0 = fmaxf(mx0, __shfl_xor_sync(0xffffffffu, mx0, 1));
        mx0 = fmaxf(mx0, __shfl_xor_sync(0xffffffffu, mx0, 2));
        mx1 = fmaxf(mx1, __shfl_xor_sync(0xffffffffu, mx1, 1));
        mx1 = fmaxf(mx1, __shfl_xor_sync(0xffffffffu, mx1, 2));
        float mn0 = fmaxf(m0, mx0), mn1 = fmaxf(m1, mx1);
        float cr0 = __expf(m0 - mn0), cr1 = __expf(m1 - mn1);
        m0 = mn0; m1 = mn1;

        const float bb0 = -mn0 * L2E, bb1 = -mn1 * L2E;
        uint32_t pLo[8], pHi[8];
        float sum0 = 0.f, sum1 = 0.f;
#pragma unroll
        for (int nt = 0; nt < 8; nt++) {
            float x0 = fmaf(s[nt][0], L2E, bb0);
            float x1 = fmaf(s[nt][1], L2E, bb0);
            float x2 = fmaf(s[nt][2], L2E, bb1);
            float x3 = fmaf(s[nt][3], L2E, bb1);
            pLo[nt] = ex2_h2(cvt_h2(x0, x1));   // {lo=exp2(x0), hi=exp2(x1)} fp16
            pHi[nt] = ex2_h2(cvt_h2(x2, x3));
            float2 fl = __half22float2(*reinterpret_cast<__half2*>(&pLo[nt]));
            float2 fh = __half22float2(*reinterpret_cast<__half2*>(&pHi[nt]));
            sum0 += fl.x + fl.y;
            sum1 += fh.x + fh.y;
        }
        sum0 += __shfl_xor_sync(0xffffffffu, sum0, 1);
        sum0 += __shfl_xor_sync(0xffffffffu, sum0, 2);
        sum1 += __shfl_xor_sync(0xffffffffu, sum1, 1);
        sum1 += __shfl_xor_sync(0xffffffffu, sum1, 2);
        l0 = l0 * cr0 + sum0;
        l1 = l1 * cr1 + sum1;
#pragma unroll
        for (int nt = 0; nt < 16; nt++) {
            o[nt][0] *= cr0; o[nt][1] *= cr0;
            o[nt][2] *= cr1; o[nt][3] *= cr1;
        }

        // O += P V  (P fragments already fp16-packed from ex2)
#pragma unroll
        for (int kc = 0; kc < 4; kc++) {
            uint32_t pH[4];
            pH[0] = pLo[2 * kc];
            pH[1] = pHi[2 * kc];
            pH[2] = pLo[2 * kc + 1];
            pH[3] = pHi[2 * kc + 1];

            uint32_t vbase = b_vr + vO + kc * (16 * AST);
#pragma unroll
            for (int ng = 0; ng < 8; ng++) {
                uint32_t vH[4];
                ldsm4t(vH, vbase + ng * 32);
                mma_f16(o[2 * ng],     pH, vH);
                mma_f16(o[2 * ng + 1], pH, vH + 2);
            }
        }
    }

    // Epilogue: normalize, fp16 store
    float inv0 = 1.f / l0, inv1 = 1.f / l1;
    int row0 = b * SEQ + qt * 64 + wid * 16 + (lane >> 2);
#pragma unroll
    for (int nt = 0; nt < 16; nt++) {
        int col = h * HDIM + nt * 8 + (lane & 3) * 2;
        *(uint32_t*)&ao[(size_t)row0 * HID + col] =
            pack_h2(o[nt][0] * inv0, o[nt][1] * inv0);
        *(uint32_t*)&ao[(size_t)(row0 + 8) * HID + col] =
            pack_h2(o[nt][2] * inv1, o[nt][3] * inv1);
    }
}

// ---------------------------------------------------------------------------
// Launch
// ---------------------------------------------------------------------------
extern "C" void kernel_launch(void* const* d_in, const int* in_sizes, int n_in,
                              void* d_out, int out_size) {
    const float* hs = (const float*)d_in[0];
    const float* Wq = (const float*)d_in[1];
    const float* Wk = (const float*)d_in[2];
    const float* Wv = (const float*)d_in[3];
    const float* Wo = (const float*)d_in[4];
    float* out = (float*)d_out;

    float *cosT, *sinT;
    cudaGetSymbolAddress((void**)&cosT, g_cosT);
    cudaGetSymbolAddress((void**)&sinT, g_sinT);

    __half *hsp, *aop, *wp, *qp, *kp, *vp;
    cudaGetSymbolAddress((void**)&hsp, g_hs);
    cudaGetSymbolAddress((void**)&aop, g_ao);
    cudaGetSymbolAddress((void**)&wp,  g_w);
    cudaGetSymbolAddress((void**)&qp,  g_q);
    cudaGetSymbolAddress((void**)&kp,  g_k);
    cudaGetSymbolAddress((void**)&vp,  g_v);

    const size_t WN = (size_t)HID * HID;
    const int n4_hs = MTOT * HID / 4;
    const int n4_w  = (int)(WN / 4);

    cvt_kernel<<<(n4_hs + 255) / 256, 256>>>(hs, hsp, n4_hs);
    cvt_w4<<<dim3((n4_w + 255) / 256, 4), 256>>>(Wq, Wk, Wv, Wo, wp, n4_w);
    rope_table<<<(SEQ * 64) / 256, 256>>>(cosT, sinT);

    cudaFuncSetAttribute(gemm_mma<0>, cudaFuncAttributeMaxDynamicSharedMemorySize, GSMEM);
    cudaFuncSetAttribute(gemm_mma<2>, cudaFuncAttributeMaxDynamicSharedMemorySize, GSMEM);

    dim3 gg(HID / 128, MTOT / 128);          // (16, 32)
    dim3 gg3(HID / 128, MTOT / 128, 3);      // Q, K, V in one launch

    // QKV projections: z=0 -> Q (RoPE), z=1 -> K (RoPE), z=2 -> V
    gemm_mma<2><<<gg3, 512, GSMEM>>>(hsp,
                                     wp + 0 * WN, wp + 1 * WN, wp + 2 * WN,
                                     nullptr,
                                     qp, kp, vp, cosT, sinT);

    cudaFuncSetAttribute(attn_tc, cudaFuncAttributeMaxDynamicSharedMemorySize, ASMEM);
    attn_tc<<<dim3(SEQ / 64, BATCH * NHEADS), 128, ASMEM>>>(qp, kp, vp, aop);

    // Output projection, fp32 store
    gemm_mma<0><<<gg, 512, GSMEM>>>(aop,
                                    wp + 3 * WN, nullptr, nullptr,
                                    out,
                                    nullptr, nullptr, nullptr,
                                    nullptr, nullptr);
}